// round 4
// baseline (speedup 1.0000x reference)
#include <cuda_runtime.h>
#include <mma.h>
using namespace nvcuda;

// ---------------- scratch (allocation-free: __device__ globals) ----------------
#define T_TOK 8192
__device__ float g_qa [T_TOK*1536];   // after wq_a (+rmsnorm in-place)
__device__ float g_q  [T_TOK*3072];   // after wq_b
__device__ float g_kva[T_TOK*576];    // after wkv_a
__device__ float g_kvn[T_TOK*512];    // normalized kv latent
__device__ float g_kpe[T_TOK*64];     // roped k_pe
__device__ float g_kv [T_TOK*4096];   // after wkv_b
__device__ float g_ao [T_TOK*2048];   // attention output

// ---------------- cp.async helpers ----------------
__device__ __forceinline__ void cp_async16(void* smem_dst, const void* gmem_src) {
    unsigned saddr = (unsigned)__cvta_generic_to_shared(smem_dst);
    asm volatile("cp.async.cg.shared.global [%0], [%1], 16;\n" :: "r"(saddr), "l"(gmem_src));
}
__device__ __forceinline__ void cp_commit() { asm volatile("cp.async.commit_group;\n"); }
template<int N> __device__ __forceinline__ void cp_wait() {
    asm volatile("cp.async.wait_group %0;\n" :: "n"(N));
}

// ---------------- pipelined TF32 GEMM: C[M,N] = A[M,K] @ W[N,K]^T + bias[N] ----
// BM=128, BK=32, 256 threads. Double-buffered cp.async stages; epilogue staged
// through the (reused) shared buffer for coalesced bias+store.
template<int BN, int WARPS_M, int WARPS_N>
__global__ __launch_bounds__(256) void gemm_big(
    const float* __restrict__ A, const float* __restrict__ W,
    const float* __restrict__ bias, float* __restrict__ C,
    int M, int N, int K)
{
    constexpr int BM = 128, BK = 32, LDS = BK + 8;            // LDS=40: bank skew
    constexpr int WM = BM / WARPS_M, WN = BN / WARPS_N;
    constexpr int FM = WM / 16, FN = WN / 16;
    constexpr int A_V4 = BM * BK / 4 / 256;                   // float4 per thread (A)
    constexpr int W_V4 = BN * BK / 4 / 256;                   // float4 per thread (W)

    extern __shared__ float smem[];
    float* sA = smem;                     // 2 * BM * LDS
    float* sW = smem + 2 * BM * LDS;      // 2 * BN * LDS

    const int bm = blockIdx.y * BM, bn = blockIdx.x * BN;
    const int tid = threadIdx.x, warp = tid >> 5;
    const int wm = (warp / WARPS_N) * WM, wn = (warp % WARPS_N) * WN;

    wmma::fragment<wmma::accumulator, 16, 16, 8, float> acc[FM][FN];
#pragma unroll
    for (int i = 0; i < FM; i++)
#pragma unroll
        for (int j = 0; j < FN; j++) wmma::fill_fragment(acc[i][j], 0.0f);

    const int KT = K / BK;
    const int ar = tid >> 3, ac = (tid & 7) * 4;              // base row/col for loads

    auto load_stage = [&](int kt, int s) {
        const float* Ag = A + (size_t)(bm + ar) * K + kt * BK + ac;
        float* dA = &sA[s * BM * LDS + ar * LDS + ac];
#pragma unroll
        for (int t = 0; t < A_V4; t++)
            cp_async16(dA + t * 32 * LDS, Ag + (size_t)t * 32 * K);
        const float* Wg = W + (size_t)(bn + ar) * K + kt * BK + ac;
        float* dW = &sW[s * BN * LDS + ar * LDS + ac];
#pragma unroll
        for (int t = 0; t < W_V4; t++)
            cp_async16(dW + t * 32 * LDS, Wg + (size_t)t * 32 * K);
        cp_commit();
    };

    load_stage(0, 0);
    for (int kt = 0; kt < KT; kt++) {
        const int s = kt & 1;
        if (kt + 1 < KT) { load_stage(kt + 1, s ^ 1); cp_wait<1>(); }
        else            { cp_wait<0>(); }
        __syncthreads();

        const float* a0 = &sA[s * BM * LDS];
        const float* w0 = &sW[s * BN * LDS];
#pragma unroll
        for (int kk = 0; kk < BK; kk += 8) {
            wmma::fragment<wmma::matrix_a, 16, 16, 8, wmma::precision::tf32, wmma::row_major> af[FM];
            wmma::fragment<wmma::matrix_b, 16, 16, 8, wmma::precision::tf32, wmma::col_major> bf[FN];
#pragma unroll
            for (int i = 0; i < FM; i++) {
                wmma::load_matrix_sync(af[i], a0 + (wm + i * 16) * LDS + kk, LDS);
#pragma unroll
                for (int e = 0; e < af[i].num_elements; e++)
                    af[i].x[e] = wmma::__float_to_tf32(af[i].x[e]);
            }
#pragma unroll
            for (int j = 0; j < FN; j++) {
                wmma::load_matrix_sync(bf[j], w0 + (wn + j * 16) * LDS + kk, LDS);
#pragma unroll
                for (int e = 0; e < bf[j].num_elements; e++)
                    bf[j].x[e] = wmma::__float_to_tf32(bf[j].x[e]);
            }
#pragma unroll
            for (int i = 0; i < FM; i++)
#pragma unroll
                for (int j = 0; j < FN; j++)
                    wmma::mma_sync(acc[i][j], af[i], bf[j], acc[i][j]);
        }
        __syncthreads();
    }

    // epilogue: stage through shared (reusing stage buffers), add bias, store
    constexpr int LDC = BN + 4;
    float* sC = smem;
#pragma unroll
    for (int i = 0; i < FM; i++)
#pragma unroll
        for (int j = 0; j < FN; j++)
            wmma::store_matrix_sync(&sC[(wm + i * 16) * LDC + wn + j * 16],
                                    acc[i][j], LDC, wmma::mem_row_major);
    __syncthreads();
#pragma unroll
    for (int t = 0; t < BM * BN / 4 / 256; t++) {
        const int j = tid + t * 256;
        const int r = j / (BN / 4), c = j % (BN / 4);
        float4 v  = *(float4*)&sC[r * LDC + c * 4];
        float4 bq = *(const float4*)(bias + bn + c * 4);
        v.x += bq.x; v.y += bq.y; v.z += bq.z; v.w += bq.w;
        *(float4*)(C + (size_t)(bm + r) * N + bn + c * 4) = v;
    }
}

// ---------------- RMSNorm (in-place, one block per row) ----------------
__global__ __launch_bounds__(256) void rmsnorm_inplace(
    float* __restrict__ data, const float* __restrict__ w, int W)
{
    const int t = blockIdx.x, tid = threadIdx.x;
    float* p = data + (size_t)t * W;
    float ss = 0.f;
    for (int i = tid; i < W; i += 256) { float v = p[i]; ss += v * v; }
    __shared__ float red[256];
    red[tid] = ss; __syncthreads();
    for (int w2 = 128; w2 > 0; w2 >>= 1) {
        if (tid < w2) red[tid] += red[tid + w2];
        __syncthreads();
    }
    const float inv = rsqrtf(red[0] / (float)W + 1.1920929e-7f);
    for (int i = tid; i < W; i += 256) p[i] = p[i] * inv * w[i];
}

// ---------------- kv_a post-process: rmsnorm(512) + rope(last 64) ----------------
__global__ __launch_bounds__(128) void kv_prep(
    const float* __restrict__ kva, const float* __restrict__ knw,
    const float* __restrict__ cosb, const float* __restrict__ sinb,
    float* __restrict__ kvn, float* __restrict__ kpe, int S)
{
    const int t = blockIdx.x, tid = threadIdx.x;
    const int s = t % S;
    const float* src = kva + (size_t)t * 576;
    float ss = 0.f;
    for (int i = tid; i < 512; i += 128) { float v = src[i]; ss += v * v; }
    __shared__ float red[128];
    red[tid] = ss; __syncthreads();
    for (int w2 = 64; w2 > 0; w2 >>= 1) {
        if (tid < w2) red[tid] += red[tid + w2];
        __syncthreads();
    }
    const float inv = rsqrtf(red[0] / 512.0f + 1.1920929e-7f);
    for (int i = tid; i < 512; i += 128) kvn[(size_t)t * 512 + i] = src[i] * inv * knw[i];
    if (tid < 32) {
        const int j = tid;
        const float c = cosb[s * 32 + j], sn = sinb[s * 32 + j];
        const float x0 = src[512 + 2 * j], x1 = src[512 + 2 * j + 1];
        kpe[(size_t)t * 64 + 2 * j]     = x0 * c  - x1 * sn;
        kpe[(size_t)t * 64 + 2 * j + 1] = x0 * sn + x1 * c;
    }
}

// ---------------- per-token attention: rope(q_pe) + 16x16 scores + softmax + attn@V ----------------
#define ATT_SCALE 0.07216878364870322f  // (128+64)^-0.5
__global__ __launch_bounds__(128) void attn_kernel(
    const float* __restrict__ q, const float* __restrict__ kv,
    const float* __restrict__ kpe, const float* __restrict__ cosb,
    const float* __restrict__ sinb, float* __restrict__ out, int S)
{
    const int t = blockIdx.x, tid = threadIdx.x;
    const int s = t % S;
    __shared__ float qs[3072];
    __shared__ float kvs[16 * 260];
    __shared__ float kp[64];
    __shared__ float sc[16][17];

    const float* qg = q + (size_t)t * 3072;
    for (int i = tid; i < 768; i += 128) ((float4*)qs)[i] = ((const float4*)qg)[i];
    const float* kvg = kv + (size_t)t * 4096;
    for (int i = tid; i < 1024; i += 128) {
        int g = i >> 6, c = i & 63;
        *(float4*)&kvs[g * 260 + c * 4] = *(const float4*)(kvg + g * 256 + c * 4);
    }
    if (tid < 16) ((float4*)kp)[tid] = ((const float4*)(kpe + (size_t)t * 64))[tid];
    __syncthreads();

    for (int p = tid; p < 512; p += 128) {
        const int h = p >> 5, j = p & 31;
        const float c = cosb[s * 32 + j], sn = sinb[s * 32 + j];
        const int i0 = h * 192 + 128 + 2 * j;
        const float x0 = qs[i0], x1 = qs[i0 + 1];
        qs[i0]     = x0 * c  - x1 * sn;
        qs[i0 + 1] = x0 * sn + x1 * c;
    }
    __syncthreads();

    {
        const int h = tid >> 3, g0 = tid & 7, g1 = g0 + 8;
        const float* qh = &qs[h * 192];
        const float* k0 = &kvs[g0 * 260];
        const float* k1 = &kvs[g1 * 260];
        float a0 = 0.f, a1 = 0.f;
#pragma unroll 8
        for (int d = 0; d < 128; d++) { const float qd = qh[d]; a0 += qd * k0[d]; a1 += qd * k1[d]; }
        float pe = 0.f;
        const float* qp = &qs[h * 192 + 128];
#pragma unroll 8
        for (int d = 0; d < 64; d++) pe += qp[d] * kp[d];
        sc[h][g0] = (a0 + pe) * ATT_SCALE;
        sc[h][g1] = (a1 + pe) * ATT_SCALE;
    }
    __syncthreads();

    if (tid < 16) {
        float m = -1e30f;
#pragma unroll
        for (int g = 0; g < 16; g++) m = fmaxf(m, sc[tid][g]);
        float sum = 0.f;
#pragma unroll
        for (int g = 0; g < 16; g++) { const float e = expf(sc[tid][g] - m); sc[tid][g] = e; sum += e; }
        const float r = 1.f / sum;
#pragma unroll
        for (int g = 0; g < 16; g++) sc[tid][g] *= r;
    }
    __syncthreads();

    for (int o = tid; o < 2048; o += 128) {
        const int h = o >> 7, d = o & 127;
        float acc = 0.f;
#pragma unroll
        for (int g = 0; g < 16; g++) acc += sc[h][g] * kvs[g * 260 + 128 + d];
        out[(size_t)t * 2048 + o] = acc;
    }
}

// ---------------- host launcher ----------------
extern "C" void kernel_launch(void* const* d_in, const int* in_sizes, int n_in,
                              void* d_out, int out_size)
{
    const float* x     = (const float*)d_in[0];
    const float* fcos  = (const float*)d_in[1];
    const float* fsin  = (const float*)d_in[2];
    const float* wqa   = (const float*)d_in[3];
    const float* wqab  = (const float*)d_in[4];
    const float* qnw   = (const float*)d_in[5];
    const float* wqb   = (const float*)d_in[6];
    const float* wqbb  = (const float*)d_in[7];
    const float* wkva  = (const float*)d_in[8];
    const float* wkvab = (const float*)d_in[9];
    const float* kvnw  = (const float*)d_in[10];
    const float* wkvb  = (const float*)d_in[11];
    const float* wkvbb = (const float*)d_in[12];
    const float* wo    = (const float*)d_in[13];
    const float* wob   = (const float*)d_in[14];
    float* out = (float*)d_out;

    const int T = in_sizes[0] / 2048;   // B*S tokens (8192)
    const int S = in_sizes[1] / 32;     // 2048

    float *qa, *qq, *kva, *kvn, *kpe, *kv, *ao;
    cudaGetSymbolAddress((void**)&qa,  g_qa);
    cudaGetSymbolAddress((void**)&qq,  g_q);
    cudaGetSymbolAddress((void**)&kva, g_kva);
    cudaGetSymbolAddress((void**)&kvn, g_kvn);
    cudaGetSymbolAddress((void**)&kpe, g_kpe);
    cudaGetSymbolAddress((void**)&kv,  g_kv);
    cudaGetSymbolAddress((void**)&ao,  g_ao);

    // shared sizes: BN=128 -> 2*(128+128)*40*4 = 81920 B; BN=64 -> 2*(128+64)*40*4 = 61440 B
    constexpr int SMEM128 = 2 * (128 + 128) * 40 * 4;
    constexpr int SMEM64  = 2 * (128 + 64)  * 40 * 4;
    cudaFuncSetAttribute(gemm_big<128,2,4>, cudaFuncAttributeMaxDynamicSharedMemorySize, SMEM128);
    cudaFuncSetAttribute(gemm_big<64,4,2>,  cudaFuncAttributeMaxDynamicSharedMemorySize, SMEM64);

    const dim3 blk(256);
    // q path
    gemm_big<128,2,4><<<dim3(1536/128, T/128), blk, SMEM128>>>(x,   wqa,  wqab,  qa,  T, 1536, 2048);
    rmsnorm_inplace<<<T, 256>>>(qa, qnw, 1536);
    gemm_big<128,2,4><<<dim3(3072/128, T/128), blk, SMEM128>>>(qa,  wqb,  wqbb,  qq,  T, 3072, 1536);
    // kv path
    gemm_big<64,4,2><<<dim3(576/64, T/128), blk, SMEM64>>>(x,   wkva, wkvab, kva, T, 576,  2048);
    kv_prep<<<T, 128>>>(kva, kvnw, fcos, fsin, kvn, kpe, S);
    gemm_big<128,2,4><<<dim3(4096/128, T/128), blk, SMEM128>>>(kvn, wkvb, wkvbb, kv,  T, 4096, 512);
    // attention + output projection
    attn_kernel<<<T, 128>>>(qq, kv, kpe, fcos, fsin, ao, S);
    gemm_big<128,2,4><<<dim3(2048/128, T/128), blk, SMEM128>>>(ao,  wo,   wob,   out, T, 2048, 2048);
}

// round 7
// speedup vs baseline: 1.3597x; 1.3597x over previous
#include <cuda_runtime.h>
#include <cstdint>

// ---------------- scratch (allocation-free: __device__ globals) ----------------
#define T_TOK 8192
__device__ float g_qa [T_TOK*1536];   // after wq_a (+rmsnorm in-place)
__device__ float g_q  [T_TOK*3072];   // after wq_b
__device__ float g_kva[T_TOK*576];    // after wkv_a
__device__ float g_kvn[T_TOK*512];    // normalized kv latent
__device__ float g_kpe[T_TOK*64];     // roped k_pe
__device__ float g_kv [T_TOK*4096];   // after wkv_b
__device__ float g_ao [T_TOK*2048];   // attention output

// ---------------- PTX helpers (arch-generic: sm_80+) ----------------
__device__ __forceinline__ void cp_async16(void* dst, const void* src) {
    unsigned s = (unsigned)__cvta_generic_to_shared(dst);
    asm volatile("cp.async.cg.shared.global [%0], [%1], 16;\n" :: "r"(s), "l"(src));
}
__device__ __forceinline__ void cp_commit() { asm volatile("cp.async.commit_group;\n"); }
template<int N> __device__ __forceinline__ void cp_wait() {
    asm volatile("cp.async.wait_group %0;\n" :: "n"(N));
}
__device__ __forceinline__ uint32_t f2tf32(float x) {
    uint32_t r;
    asm("cvt.rna.tf32.f32 %0, %1;" : "=r"(r) : "f"(x));
    return r;
}
__device__ __forceinline__ void mma1688(float* d, const uint32_t* a, const uint32_t* b) {
    asm volatile(
        "mma.sync.aligned.m16n8k8.row.col.f32.tf32.tf32.f32 "
        "{%0,%1,%2,%3}, {%4,%5,%6,%7}, {%8,%9}, {%0,%1,%2,%3};"
        : "+f"(d[0]), "+f"(d[1]), "+f"(d[2]), "+f"(d[3])
        : "r"(a[0]), "r"(a[1]), "r"(a[2]), "r"(a[3]), "r"(b[0]), "r"(b[1]));
}

// ---------------- tf32 mma.sync GEMM: C[M,N] = A[M,K] @ W[N,K]^T + bias[N] ----
// BM=BN=128, BK=32, 256 threads (8 warps, 2x4), warp tile 64x32 (4x4 m16n8k8).
// 2-stage cp.async double buffer; LDS stride 36 -> conflict-free fragment loads.
// 2 CTAs/SM (74KB smem, <=128 regs). M%128==0; N arbitrary (B-row clamp + store guard).
#define GLDS 36
#define TILE_F (128 * GLDS)             // floats per tile (A or B)
#define STG_F  (2 * TILE_F)             // floats per stage (A+B)
#define GEMM_SMEM ((2 * STG_F + 128) * 4)

__global__ __launch_bounds__(256, 2) void gemm_mma(
    const float* __restrict__ A, const float* __restrict__ W,
    const float* __restrict__ bias, float* __restrict__ C,
    int M, int N, int K)
{
    extern __shared__ float smem[];
    float* sBias = smem + 2 * STG_F;

    const int tid = threadIdx.x, warp = tid >> 5, lane = tid & 31;
    const int gid = lane >> 2, tig = lane & 3;
    const int bm = blockIdx.y * 128, bn = blockIdx.x * 128;
    const int wm = (warp >> 2) * 64, wn = (warp & 3) * 32;
    const int KT = K / 32;

    if (tid < 128) {
        int c = bn + tid;
        sBias[tid] = (c < N) ? bias[c] : 0.0f;
    }

    float acc[4][4][4];
#pragma unroll
    for (int i = 0; i < 4; i++)
#pragma unroll
        for (int j = 0; j < 4; j++)
#pragma unroll
            for (int r = 0; r < 4; r++) acc[i][j][r] = 0.0f;

    // loader: 2048 16B-chunks per stage (A:1024, B:1024), 8 per thread
    const int lrow = tid >> 3, lc16 = tid & 7;           // tid -> (row, 16B col) base
    auto load_stage = [&](int kt) {
        float* st = smem + (kt & 1) * STG_F;
        const int k0 = kt * 32;
#pragma unroll
        for (int i = 0; i < 4; i++) {
            const int row = lrow + i * 32;
            cp_async16(st + row * GLDS + lc16 * 4,
                       A + (size_t)(bm + row) * K + k0 + lc16 * 4);
            int rB = bn + row; if (rB >= N) rB = N - 1;  // clamp; junk cols never stored
            cp_async16(st + TILE_F + row * GLDS + lc16 * 4,
                       W + (size_t)rB * K + k0 + lc16 * 4);
        }
        cp_commit();
    };

    load_stage(0);
    for (int kt = 0; kt < KT; kt++) {
        if (kt + 1 < KT) { load_stage(kt + 1); cp_wait<1>(); }
        else             { cp_wait<0>(); }
        __syncthreads();

        const float* sa = smem + (kt & 1) * STG_F;
        const float* sw = sa + TILE_F;
#pragma unroll
        for (int kk = 0; kk < 4; kk++) {
            const int k = kk * 8;
            uint32_t Af[4][4], Bf[4][2];
#pragma unroll
            for (int i = 0; i < 4; i++) {
                const float* p = sa + (wm + i * 16 + gid) * GLDS + k + tig;
                Af[i][0] = f2tf32(p[0]);
                Af[i][1] = f2tf32(p[8 * GLDS]);
                Af[i][2] = f2tf32(p[4]);
                Af[i][3] = f2tf32(p[8 * GLDS + 4]);
            }
#pragma unroll
            for (int j = 0; j < 4; j++) {
                const float* p = sw + (wn + j * 8 + gid) * GLDS + k + tig;
                Bf[j][0] = f2tf32(p[0]);
                Bf[j][1] = f2tf32(p[4]);
            }
#pragma unroll
            for (int i = 0; i < 4; i++)
#pragma unroll
                for (int j = 0; j < 4; j++)
                    mma1688(acc[i][j], Af[i], Bf[j]);
        }
        __syncthreads();
    }

    // epilogue: direct float2 stores (+bias); 4-lane groups cover 128B per row
#pragma unroll
    for (int i = 0; i < 4; i++) {
        const int r0 = bm + wm + i * 16 + gid;
        const int r1 = r0 + 8;
#pragma unroll
        for (int j = 0; j < 4; j++) {
            const int c = wn + j * 8 + tig * 2;
            if (bn + c < N) {
                const float b0 = sBias[c], b1 = sBias[c + 1];
                float2 v0 = {acc[i][j][0] + b0, acc[i][j][1] + b1};
                float2 v1 = {acc[i][j][2] + b0, acc[i][j][3] + b1};
                *(float2*)(C + (size_t)r0 * N + bn + c) = v0;
                *(float2*)(C + (size_t)r1 * N + bn + c) = v1;
            }
        }
    }
}

// ---------------- RMSNorm (in-place, one block per row) ----------------
__global__ __launch_bounds__(256) void rmsnorm_inplace(
    float* __restrict__ data, const float* __restrict__ w, int W)
{
    const int t = blockIdx.x, tid = threadIdx.x;
    float* p = data + (size_t)t * W;
    float ss = 0.f;
    for (int i = tid; i < W; i += 256) { float v = p[i]; ss += v * v; }
    __shared__ float red[256];
    red[tid] = ss; __syncthreads();
    for (int w2 = 128; w2 > 0; w2 >>= 1) {
        if (tid < w2) red[tid] += red[tid + w2];
        __syncthreads();
    }
    const float inv = rsqrtf(red[0] / (float)W + 1.1920929e-7f);
    for (int i = tid; i < W; i += 256) p[i] = p[i] * inv * w[i];
}

// ---------------- kv_a post-process: rmsnorm(512) + rope(last 64) ----------------
__global__ __launch_bounds__(128) void kv_prep(
    const float* __restrict__ kva, const float* __restrict__ knw,
    const float* __restrict__ cosb, const float* __restrict__ sinb,
    float* __restrict__ kvn, float* __restrict__ kpe, int S)
{
    const int t = blockIdx.x, tid = threadIdx.x;
    const int s = t % S;
    const float* src = kva + (size_t)t * 576;
    float ss = 0.f;
    for (int i = tid; i < 512; i += 128) { float v = src[i]; ss += v * v; }
    __shared__ float red[128];
    red[tid] = ss; __syncthreads();
    for (int w2 = 64; w2 > 0; w2 >>= 1) {
        if (tid < w2) red[tid] += red[tid + w2];
        __syncthreads();
    }
    const float inv = rsqrtf(red[0] / 512.0f + 1.1920929e-7f);
    for (int i = tid; i < 512; i += 128) kvn[(size_t)t * 512 + i] = src[i] * inv * knw[i];
    if (tid < 32) {
        const int j = tid;
        const float c = cosb[s * 32 + j], sn = sinb[s * 32 + j];
        const float x0 = src[512 + 2 * j], x1 = src[512 + 2 * j + 1];
        kpe[(size_t)t * 64 + 2 * j]     = x0 * c  - x1 * sn;
        kpe[(size_t)t * 64 + 2 * j + 1] = x0 * sn + x1 * c;
    }
}

// ---------------- per-token attention: rope(q_pe) + 16x16 scores + softmax + attn@V ----------------
#define ATT_SCALE 0.07216878364870322f  // (128+64)^-0.5
__global__ __launch_bounds__(128) void attn_kernel(
    const float* __restrict__ q, const float* __restrict__ kv,
    const float* __restrict__ kpe, const float* __restrict__ cosb,
    const float* __restrict__ sinb, float* __restrict__ out, int S)
{
    const int t = blockIdx.x, tid = threadIdx.x;
    const int s = t % S;
    __shared__ float qs[3072];
    __shared__ float kvs[16 * 260];
    __shared__ float kp[64];
    __shared__ float sc[16][17];

    const float* qg = q + (size_t)t * 3072;
    for (int i = tid; i < 768; i += 128) ((float4*)qs)[i] = ((const float4*)qg)[i];
    const float* kvg = kv + (size_t)t * 4096;
    for (int i = tid; i < 1024; i += 128) {
        int g = i >> 6, c = i & 63;
        *(float4*)&kvs[g * 260 + c * 4] = *(const float4*)(kvg + g * 256 + c * 4);
    }
    if (tid < 16) ((float4*)kp)[tid] = ((const float4*)(kpe + (size_t)t * 64))[tid];
    __syncthreads();

    for (int p = tid; p < 512; p += 128) {
        const int h = p >> 5, j = p & 31;
        const float c = cosb[s * 32 + j], sn = sinb[s * 32 + j];
        const int i0 = h * 192 + 128 + 2 * j;
        const float x0 = qs[i0], x1 = qs[i0 + 1];
        qs[i0]     = x0 * c  - x1 * sn;
        qs[i0 + 1] = x0 * sn + x1 * c;
    }
    __syncthreads();

    {
        const int h = tid >> 3, g0 = tid & 7, g1 = g0 + 8;
        const float* qh = &qs[h * 192];
        const float* k0 = &kvs[g0 * 260];
        const float* k1 = &kvs[g1 * 260];
        float a0 = 0.f, a1 = 0.f;
#pragma unroll 8
        for (int d = 0; d < 128; d++) { const float qd = qh[d]; a0 += qd * k0[d]; a1 += qd * k1[d]; }
        float pe = 0.f;
        const float* qp = &qs[h * 192 + 128];
#pragma unroll 8
        for (int d = 0; d < 64; d++) pe += qp[d] * kp[d];
        sc[h][g0] = (a0 + pe) * ATT_SCALE;
        sc[h][g1] = (a1 + pe) * ATT_SCALE;
    }
    __syncthreads();

    if (tid < 16) {
        float m = -1e30f;
#pragma unroll
        for (int g = 0; g < 16; g++) m = fmaxf(m, sc[tid][g]);
        float sum = 0.f;
#pragma unroll
        for (int g = 0; g < 16; g++) { const float e = expf(sc[tid][g] - m); sc[tid][g] = e; sum += e; }
        const float r = 1.f / sum;
#pragma unroll
        for (int g = 0; g < 16; g++) sc[tid][g] *= r;
    }
    __syncthreads();

    for (int o = tid; o < 2048; o += 128) {
        const int h = o >> 7, d = o & 127;
        float acc = 0.f;
#pragma unroll
        for (int g = 0; g < 16; g++) acc += sc[h][g] * kvs[g * 260 + 128 + d];
        out[(size_t)t * 2048 + o] = acc;
    }
}

// ---------------- host launcher ----------------
static inline void launch_gemm(const float* A, const float* W, const float* bias,
                               float* C, int M, int N, int K)
{
    dim3 grid((N + 127) / 128, M / 128);
    gemm_mma<<<grid, 256, GEMM_SMEM>>>(A, W, bias, C, M, N, K);
}

extern "C" void kernel_launch(void* const* d_in, const int* in_sizes, int n_in,
                              void* d_out, int out_size)
{
    const float* x     = (const float*)d_in[0];
    const float* fcos  = (const float*)d_in[1];
    const float* fsin  = (const float*)d_in[2];
    const float* wqa   = (const float*)d_in[3];
    const float* wqab  = (const float*)d_in[4];
    const float* qnw   = (const float*)d_in[5];
    const float* wqb   = (const float*)d_in[6];
    const float* wqbb  = (const float*)d_in[7];
    const float* wkva  = (const float*)d_in[8];
    const float* wkvab = (const float*)d_in[9];
    const float* kvnw  = (const float*)d_in[10];
    const float* wkvb  = (const float*)d_in[11];
    const float* wkvbb = (const float*)d_in[12];
    const float* wo    = (const float*)d_in[13];
    const float* wob   = (const float*)d_in[14];
    float* out = (float*)d_out;

    const int T = in_sizes[0] / 2048;   // B*S tokens (8192)
    const int S = in_sizes[1] / 32;     // 2048

    float *qa, *qq, *kva, *kvn, *kpe, *kv, *ao;
    cudaGetSymbolAddress((void**)&qa,  g_qa);
    cudaGetSymbolAddress((void**)&qq,  g_q);
    cudaGetSymbolAddress((void**)&kva, g_kva);
    cudaGetSymbolAddress((void**)&kvn, g_kvn);
    cudaGetSymbolAddress((void**)&kpe, g_kpe);
    cudaGetSymbolAddress((void**)&kv,  g_kv);
    cudaGetSymbolAddress((void**)&ao,  g_ao);

    cudaFuncSetAttribute(gemm_mma, cudaFuncAttributeMaxDynamicSharedMemorySize, GEMM_SMEM);

    // q path
    launch_gemm(x,   wqa,  wqab,  qa,  T, 1536, 2048);
    rmsnorm_inplace<<<T, 256>>>(qa, qnw, 1536);
    launch_gemm(qa,  wqb,  wqbb,  qq,  T, 3072, 1536);
    // kv path
    launch_gemm(x,   wkva, wkvab, kva, T, 576,  2048);
    kv_prep<<<T, 128>>>(kva, kvnw, fcos, fsin, kvn, kpe, S);
    launch_gemm(kvn, wkvb, wkvbb, kv,  T, 4096, 512);
    // attention + output projection
    attn_kernel<<<T, 128>>>(qq, kv, kpe, fcos, fsin, ao, S);
    launch_gemm(ao,  wo,   wob,   out, T, 2048, 2048);
}

// round 8
// speedup vs baseline: 2.3364x; 1.7183x over previous
#include <cuda_runtime.h>
#include <cstdint>

// ---------------- scratch (allocation-free: __device__ globals) ----------------
#define T_TOK 8192
__device__ float g_qa [T_TOK*1536];   // after wq_a (+rmsnorm in-place, tf32-rounded)
__device__ float g_q  [T_TOK*3072];   // after wq_b (full fp32, attention input)
__device__ float g_kva[T_TOK*576];    // after wkv_a
__device__ float g_kvn[T_TOK*512];    // normalized kv latent (tf32-rounded)
__device__ float g_kpe[T_TOK*64];     // roped k_pe
__device__ float g_kv [T_TOK*4096];   // after wkv_b (full fp32)
__device__ float g_ao [T_TOK*2048];   // attention output (tf32-rounded)
__device__ float g_xr [T_TOK*2048];   // x rounded to tf32
__device__ float g_wr [15335424];     // all 5 weight matrices rounded to tf32

#define WQA_OFF   0
#define WQB_OFF   3145728
#define WKVA_OFF  7864320
#define WKVB_OFF  9043968
#define WO_OFF    11141120

// ---------------- PTX helpers (arch-generic: sm_80+) ----------------
__device__ __forceinline__ void cp_async16(void* dst, const void* src) {
    unsigned s = (unsigned)__cvta_generic_to_shared(dst);
    asm volatile("cp.async.cg.shared.global [%0], [%1], 16;\n" :: "r"(s), "l"(src));
}
__device__ __forceinline__ void cp_commit() { asm volatile("cp.async.commit_group;\n"); }
template<int N> __device__ __forceinline__ void cp_wait() {
    asm volatile("cp.async.wait_group %0;\n" :: "n"(N));
}
__device__ __forceinline__ float tf32r(float x) {
    uint32_t r;
    asm("cvt.rna.tf32.f32 %0, %1;" : "=r"(r) : "f"(x));
    return __uint_as_float(r);
}
__device__ __forceinline__ void mma1688(float* d, const uint32_t* a, const uint32_t* b) {
    asm volatile(
        "mma.sync.aligned.m16n8k8.row.col.f32.tf32.tf32.f32 "
        "{%0,%1,%2,%3}, {%4,%5,%6,%7}, {%8,%9}, {%0,%1,%2,%3};"
        : "+f"(d[0]), "+f"(d[1]), "+f"(d[2]), "+f"(d[3])
        : "r"(a[0]), "r"(a[1]), "r"(a[2]), "r"(a[3]), "r"(b[0]), "r"(b[1]));
}
__device__ __forceinline__ void ldsm_x4(uint32_t a, uint32_t* r) {
    asm volatile("ldmatrix.sync.aligned.m8n8.x4.shared.b16 {%0,%1,%2,%3}, [%4];"
        : "=r"(r[0]), "=r"(r[1]), "=r"(r[2]), "=r"(r[3]) : "r"(a));
}
__device__ __forceinline__ void ldsm_x2(uint32_t a, uint32_t* r) {
    asm volatile("ldmatrix.sync.aligned.m8n8.x2.shared.b16 {%0,%1}, [%2];"
        : "=r"(r[0]), "=r"(r[1]) : "r"(a));
}

// ---------------- tf32 mma.sync GEMM: C[M,N] = A[M,K] @ W[N,K]^T + bias[N] ----
// BM=BN=128, BK=32, 256 threads (8 warps 2x4), warp tile 64x32 (4x4 m16n8k8).
// Inputs MUST be pre-rounded to tf32 (HW reads top bits directly, no cvt).
// 3-stage cp.async pipeline, ONE barrier per K-tile; ldmatrix fragment loads.
#define GLDS 36
#define TILE_F (128 * GLDS)               // floats per tile (A or B)
#define TILE_BYTES (TILE_F * 4)
#define STG_F  (2 * TILE_F)               // floats per stage (A+B)
#define STG_BYTES (STG_F * 4)
#define GEMM_SMEM (3 * STG_BYTES + 512)   // 111104 B

__global__ __launch_bounds__(256, 2) void gemm_mma(
    const float* __restrict__ A, const float* __restrict__ W,
    const float* __restrict__ bias, float* __restrict__ C,
    int M, int N, int K)
{
    extern __shared__ float smem[];
    float* sBias = smem + 3 * STG_F;
    const uint32_t smem_u = (uint32_t)__cvta_generic_to_shared(smem);

    const int tid = threadIdx.x, warp = tid >> 5, lane = tid & 31;
    const int gid = lane >> 2, tig = lane & 3;
    const int bm = blockIdx.y * 128, bn = blockIdx.x * 128;
    const int wm = (warp >> 2) * 64, wn = (warp & 3) * 32;
    const int KT = K / 32;

    if (tid < 128) {
        int c = bn + tid;
        sBias[tid] = (c < N) ? bias[c] : 0.0f;
    }

    float acc[4][4][4];
#pragma unroll
    for (int i = 0; i < 4; i++)
#pragma unroll
        for (int j = 0; j < 4; j++)
#pragma unroll
            for (int r = 0; r < 4; r++) acc[i][j][r] = 0.0f;

    // loader: 2048 16B-chunks per stage (A:1024, B:1024), 8 per thread
    const int lrow = tid >> 3, lc16 = tid & 7;
    auto load_stage = [&](int kt) {
        float* st = smem + (kt % 3) * STG_F;
        const int k0 = kt * 32;
#pragma unroll
        for (int i = 0; i < 4; i++) {
            const int row = lrow + i * 32;
            cp_async16(st + row * GLDS + lc16 * 4,
                       A + (size_t)(bm + row) * K + k0 + lc16 * 4);
            int rB = bn + row; if (rB >= N) rB = N - 1;   // clamp; junk cols never stored
            cp_async16(st + TILE_F + row * GLDS + lc16 * 4,
                       W + (size_t)rB * K + k0 + lc16 * 4);
        }
        cp_commit();
    };

    // per-lane ldmatrix base offsets (bytes, within a stage)
    const uint32_t aOff = 4 * ((wm + (lane & 15)) * GLDS + ((lane >> 4) << 2));
    const uint32_t bOff = TILE_BYTES + 4 * ((wn + (lane & 7)) * GLDS + (((lane >> 3) & 1) << 2));

    load_stage(0);
    load_stage(1);

    for (int kt = 0; kt < KT; kt++) {
        if (kt + 1 < KT) cp_wait<1>(); else cp_wait<0>();
        __syncthreads();                       // stage kt visible; stage (kt+2)%3 free
        if (kt + 2 < KT) load_stage(kt + 2);

        const uint32_t stg = smem_u + (kt % 3) * STG_BYTES;
        const uint32_t aB = stg + aOff;
        const uint32_t bB = stg + bOff;
#pragma unroll
        for (int kk = 0; kk < 4; kk++) {
            uint32_t Af[4][4], Bf[4][2];
#pragma unroll
            for (int i = 0; i < 4; i++)
                ldsm_x4(aB + (uint32_t)(i * 16 * GLDS + kk * 8) * 4, Af[i]);
#pragma unroll
            for (int j = 0; j < 4; j++)
                ldsm_x2(bB + (uint32_t)(j * 8 * GLDS + kk * 8) * 4, Bf[j]);
#pragma unroll
            for (int i = 0; i < 4; i++)
#pragma unroll
                for (int j = 0; j < 4; j++)
                    mma1688(acc[i][j], Af[i], Bf[j]);
        }
    }

    // epilogue: direct float2 stores (+bias)
#pragma unroll
    for (int i = 0; i < 4; i++) {
        const int r0 = bm + wm + i * 16 + gid;
        const int r1 = r0 + 8;
#pragma unroll
        for (int j = 0; j < 4; j++) {
            const int c = wn + j * 8 + tig * 2;
            if (bn + c < N) {
                const float b0 = sBias[c], b1 = sBias[c + 1];
                float2 v0 = {acc[i][j][0] + b0, acc[i][j][1] + b1};
                float2 v1 = {acc[i][j][2] + b0, acc[i][j][3] + b1};
                *(float2*)(C + (size_t)r0 * N + bn + c) = v0;
                *(float2*)(C + (size_t)r1 * N + bn + c) = v1;
            }
        }
    }
}

// ---------------- tf32 rounding prepass (float4 grid-stride) ----------------
__global__ __launch_bounds__(256) void round_tf32_k(
    const float* __restrict__ in, float* __restrict__ out, int n)
{
    int i = (blockIdx.x * 256 + threadIdx.x) * 4;
    if (i < n) {
        float4 v = *(const float4*)(in + i);
        v.x = tf32r(v.x); v.y = tf32r(v.y); v.z = tf32r(v.z); v.w = tf32r(v.w);
        *(float4*)(out + i) = v;
    }
}

// ---------------- RMSNorm (in-place; output tf32-rounded for next GEMM) ------
__global__ __launch_bounds__(256) void rmsnorm_inplace(
    float* __restrict__ data, const float* __restrict__ w, int W)
{
    const int t = blockIdx.x, tid = threadIdx.x;
    float* p = data + (size_t)t * W;
    float ss = 0.f;
    for (int i = tid; i < W; i += 256) { float v = p[i]; ss += v * v; }
    __shared__ float red[256];
    red[tid] = ss; __syncthreads();
    for (int w2 = 128; w2 > 0; w2 >>= 1) {
        if (tid < w2) red[tid] += red[tid + w2];
        __syncthreads();
    }
    const float inv = rsqrtf(red[0] / (float)W + 1.1920929e-7f);
    for (int i = tid; i < W; i += 256) p[i] = tf32r(p[i] * inv * w[i]);
}

// ---------------- kv_a post-process: rmsnorm(512, rounded) + rope(last 64) ---
__global__ __launch_bounds__(128) void kv_prep(
    const float* __restrict__ kva, const float* __restrict__ knw,
    const float* __restrict__ cosb, const float* __restrict__ sinb,
    float* __restrict__ kvn, float* __restrict__ kpe, int S)
{
    const int t = blockIdx.x, tid = threadIdx.x;
    const int s = t % S;
    const float* src = kva + (size_t)t * 576;
    float ss = 0.f;
    for (int i = tid; i < 512; i += 128) { float v = src[i]; ss += v * v; }
    __shared__ float red[128];
    red[tid] = ss; __syncthreads();
    for (int w2 = 64; w2 > 0; w2 >>= 1) {
        if (tid < w2) red[tid] += red[tid + w2];
        __syncthreads();
    }
    const float inv = rsqrtf(red[0] / 512.0f + 1.1920929e-7f);
    for (int i = tid; i < 512; i += 128)
        kvn[(size_t)t * 512 + i] = tf32r(src[i] * inv * knw[i]);
    if (tid < 32) {
        const int j = tid;
        const float c = cosb[s * 32 + j], sn = sinb[s * 32 + j];
        const float x0 = src[512 + 2 * j], x1 = src[512 + 2 * j + 1];
        kpe[(size_t)t * 64 + 2 * j]     = x0 * c  - x1 * sn;
        kpe[(size_t)t * 64 + 2 * j + 1] = x0 * sn + x1 * c;
    }
}

// ---------------- per-token attention (output tf32-rounded for wo GEMM) ------
#define ATT_SCALE 0.07216878364870322f  // (128+64)^-0.5
__global__ __launch_bounds__(128) void attn_kernel(
    const float* __restrict__ q, const float* __restrict__ kv,
    const float* __restrict__ kpe, const float* __restrict__ cosb,
    const float* __restrict__ sinb, float* __restrict__ out, int S)
{
    const int t = blockIdx.x, tid = threadIdx.x;
    const int s = t % S;
    __shared__ float qs[3072];
    __shared__ float kvs[16 * 260];
    __shared__ float kp[64];
    __shared__ float sc[16][17];

    const float* qg = q + (size_t)t * 3072;
    for (int i = tid; i < 768; i += 128) ((float4*)qs)[i] = ((const float4*)qg)[i];
    const float* kvg = kv + (size_t)t * 4096;
    for (int i = tid; i < 1024; i += 128) {
        int g = i >> 6, c = i & 63;
        *(float4*)&kvs[g * 260 + c * 4] = *(const float4*)(kvg + g * 256 + c * 4);
    }
    if (tid < 16) ((float4*)kp)[tid] = ((const float4*)(kpe + (size_t)t * 64))[tid];
    __syncthreads();

    for (int p = tid; p < 512; p += 128) {
        const int h = p >> 5, j = p & 31;
        const float c = cosb[s * 32 + j], sn = sinb[s * 32 + j];
        const int i0 = h * 192 + 128 + 2 * j;
        const float x0 = qs[i0], x1 = qs[i0 + 1];
        qs[i0]     = x0 * c  - x1 * sn;
        qs[i0 + 1] = x0 * sn + x1 * c;
    }
    __syncthreads();

    {
        const int h = tid >> 3, g0 = tid & 7, g1 = g0 + 8;
        const float* qh = &qs[h * 192];
        const float* k0 = &kvs[g0 * 260];
        const float* k1 = &kvs[g1 * 260];
        float a0 = 0.f, a1 = 0.f;
#pragma unroll 8
        for (int d = 0; d < 128; d++) { const float qd = qh[d]; a0 += qd * k0[d]; a1 += qd * k1[d]; }
        float pe = 0.f;
        const float* qp = &qs[h * 192 + 128];
#pragma unroll 8
        for (int d = 0; d < 64; d++) pe += qp[d] * kp[d];
        sc[h][g0] = (a0 + pe) * ATT_SCALE;
        sc[h][g1] = (a1 + pe) * ATT_SCALE;
    }
    __syncthreads();

    if (tid < 16) {
        float m = -1e30f;
#pragma unroll
        for (int g = 0; g < 16; g++) m = fmaxf(m, sc[tid][g]);
        float sum = 0.f;
#pragma unroll
        for (int g = 0; g < 16; g++) { const float e = expf(sc[tid][g] - m); sc[tid][g] = e; sum += e; }
        const float r = 1.f / sum;
#pragma unroll
        for (int g = 0; g < 16; g++) sc[tid][g] *= r;
    }
    __syncthreads();

    for (int o = tid; o < 2048; o += 128) {
        const int h = o >> 7, d = o & 127;
        float acc = 0.f;
#pragma unroll
        for (int g = 0; g < 16; g++) acc += sc[h][g] * kvs[g * 260 + 128 + d];
        out[(size_t)t * 2048 + o] = tf32r(acc);
    }
}

// ---------------- host launcher ----------------
static inline void launch_gemm(const float* A, const float* W, const float* bias,
                               float* C, int M, int N, int K)
{
    dim3 grid((N + 127) / 128, M / 128);
    gemm_mma<<<grid, 256, GEMM_SMEM>>>(A, W, bias, C, M, N, K);
}
static inline void launch_round(const float* in, float* out, int n)
{
    round_tf32_k<<<(n / 4 + 255) / 256, 256>>>(in, out, n);
}

extern "C" void kernel_launch(void* const* d_in, const int* in_sizes, int n_in,
                              void* d_out, int out_size)
{
    const float* x     = (const float*)d_in[0];
    const float* fcos  = (const float*)d_in[1];
    const float* fsin  = (const float*)d_in[2];
    const float* wqa   = (const float*)d_in[3];
    const float* wqab  = (const float*)d_in[4];
    const float* qnw   = (const float*)d_in[5];
    const float* wqb   = (const float*)d_in[6];
    const float* wqbb  = (const float*)d_in[7];
    const float* wkva  = (const float*)d_in[8];
    const float* wkvab = (const float*)d_in[9];
    const float* kvnw  = (const float*)d_in[10];
    const float* wkvb  = (const float*)d_in[11];
    const float* wkvbb = (const float*)d_in[12];
    const float* wo    = (const float*)d_in[13];
    const float* wob   = (const float*)d_in[14];
    float* out = (float*)d_out;

    const int T = in_sizes[0] / 2048;   // B*S tokens (8192)
    const int S = in_sizes[1] / 32;     // 2048

    float *qa, *qq, *kva, *kvn, *kpe, *kv, *ao, *xr, *wr;
    cudaGetSymbolAddress((void**)&qa,  g_qa);
    cudaGetSymbolAddress((void**)&qq,  g_q);
    cudaGetSymbolAddress((void**)&kva, g_kva);
    cudaGetSymbolAddress((void**)&kvn, g_kvn);
    cudaGetSymbolAddress((void**)&kpe, g_kpe);
    cudaGetSymbolAddress((void**)&kv,  g_kv);
    cudaGetSymbolAddress((void**)&ao,  g_ao);
    cudaGetSymbolAddress((void**)&xr,  g_xr);
    cudaGetSymbolAddress((void**)&wr,  g_wr);

    cudaFuncSetAttribute(gemm_mma, cudaFuncAttributeMaxDynamicSharedMemorySize, GEMM_SMEM);

    // prepass: round x + all weights to tf32 (bit-exact with per-fragment cvt)
    launch_round(x,    xr,             T * 2048);
    launch_round(wqa,  wr + WQA_OFF,   1536 * 2048);
    launch_round(wqb,  wr + WQB_OFF,   3072 * 1536);
    launch_round(wkva, wr + WKVA_OFF,  576 * 2048);
    launch_round(wkvb, wr + WKVB_OFF,  4096 * 512);
    launch_round(wo,   wr + WO_OFF,    2048 * 2048);

    // q path
    launch_gemm(xr,  wr + WQA_OFF,  wqab,  qa,  T, 1536, 2048);
    rmsnorm_inplace<<<T, 256>>>(qa, qnw, 1536);
    launch_gemm(qa,  wr + WQB_OFF,  wqbb,  qq,  T, 3072, 1536);
    // kv path
    launch_gemm(xr,  wr + WKVA_OFF, wkvab, kva, T, 576,  2048);
    kv_prep<<<T, 128>>>(kva, kvnw, fcos, fsin, kvn, kpe, S);
    launch_gemm(kvn, wr + WKVB_OFF, wkvbb, kv,  T, 4096, 512);
    // attention + output projection
    attn_kernel<<<T, 128>>>(qq, kv, kpe, fcos, fsin, ao, S);
    launch_gemm(ao,  wr + WO_OFF,   wob,   out, T, 2048, 2048);
}

// round 9
// speedup vs baseline: 2.3869x; 1.0216x over previous
#include <cuda_runtime.h>
#include <cstdint>

// ---------------- scratch (allocation-free: __device__ globals) ----------------
#define T_TOK 8192
__device__ float g_qa [T_TOK*1536];   // after wq_a (+rmsnorm in-place, tf32-rounded)
__device__ float g_q  [T_TOK*3072];   // after wq_b (full fp32, attention input)
__device__ float g_kva[T_TOK*576];    // after wkv_a
__device__ float g_kvn[T_TOK*512];    // normalized kv latent (tf32-rounded)
__device__ float g_kpe[T_TOK*64];     // roped k_pe
__device__ float g_kv [T_TOK*4096];   // after wkv_b (full fp32)
__device__ float g_ao [T_TOK*2048];   // attention output (tf32-rounded)
__device__ float g_xr [T_TOK*2048];   // x rounded to tf32
__device__ float g_wr [15335424];     // all 5 weight matrices rounded to tf32

#define WQA_OFF   0
#define WQB_OFF   3145728
#define WKVA_OFF  7864320
#define WKVB_OFF  9043968
#define WO_OFF    11141120

// ---------------- PTX helpers (arch-generic: sm_80+) ----------------
__device__ __forceinline__ void cp_async16(void* dst, const void* src) {
    unsigned s = (unsigned)__cvta_generic_to_shared(dst);
    asm volatile("cp.async.cg.shared.global [%0], [%1], 16;\n" :: "r"(s), "l"(src));
}
__device__ __forceinline__ void cp_commit() { asm volatile("cp.async.commit_group;\n"); }
template<int N> __device__ __forceinline__ void cp_wait() {
    asm volatile("cp.async.wait_group %0;\n" :: "n"(N));
}
__device__ __forceinline__ float tf32r(float x) {
    uint32_t r;
    asm("cvt.rna.tf32.f32 %0, %1;" : "=r"(r) : "f"(x));
    return __uint_as_float(r);
}
__device__ __forceinline__ void mma1688(float* d, const uint32_t* a, const uint32_t* b) {
    asm volatile(
        "mma.sync.aligned.m16n8k8.row.col.f32.tf32.tf32.f32 "
        "{%0,%1,%2,%3}, {%4,%5,%6,%7}, {%8,%9}, {%0,%1,%2,%3};"
        : "+f"(d[0]), "+f"(d[1]), "+f"(d[2]), "+f"(d[3])
        : "r"(a[0]), "r"(a[1]), "r"(a[2]), "r"(a[3]), "r"(b[0]), "r"(b[1]));
}
__device__ __forceinline__ void ldsm_x4(uint32_t a, uint32_t* r) {
    asm volatile("ldmatrix.sync.aligned.m8n8.x4.shared.b16 {%0,%1,%2,%3}, [%4];"
        : "=r"(r[0]), "=r"(r[1]), "=r"(r[2]), "=r"(r[3]) : "r"(a));
}

// ---------------- tf32 mma.sync GEMM: C[M,N] = A[M,K] @ W[N,K]^T + bias[N] ----
// BM=BN=128, BK=32, 256 threads (8 warps 2x4), warp tile 64x32 (4x4 m16n8k8).
// Inputs MUST be pre-rounded to tf32. 3-stage cp.async pipeline, ONE barrier
// per K-tile; ldmatrix.x4 fragment loads (A: 4, B: 2 per kk) double-buffered
// across kk so LDSM latency hides under the HMMA burst.
#define GLDS 36
#define TILE_F (128 * GLDS)               // floats per tile (A or B)
#define TILE_BYTES (TILE_F * 4)
#define STG_F  (2 * TILE_F)               // floats per stage (A+B)
#define STG_BYTES (STG_F * 4)
#define GEMM_SMEM (3 * STG_BYTES + 512)   // 111104 B

__global__ __launch_bounds__(256, 2) void gemm_mma(
    const float* __restrict__ A, const float* __restrict__ W,
    const float* __restrict__ bias, float* __restrict__ C,
    int M, int N, int K)
{
    extern __shared__ float smem[];
    float* sBias = smem + 3 * STG_F;
    const uint32_t smem_u = (uint32_t)__cvta_generic_to_shared(smem);

    const int tid = threadIdx.x, warp = tid >> 5, lane = tid & 31;
    const int gid = lane >> 2, tig = lane & 3;
    const int bm = blockIdx.y * 128, bn = blockIdx.x * 128;
    const int wm = (warp >> 2) * 64, wn = (warp & 3) * 32;
    const int KT = K / 32;

    if (tid < 128) {
        int c = bn + tid;
        sBias[tid] = (c < N) ? bias[c] : 0.0f;
    }

    float acc[4][4][4];
#pragma unroll
    for (int i = 0; i < 4; i++)
#pragma unroll
        for (int j = 0; j < 4; j++)
#pragma unroll
            for (int r = 0; r < 4; r++) acc[i][j][r] = 0.0f;

    // loader: 2048 16B-chunks per stage (A:1024, B:1024), 8 per thread
    const int lrow = tid >> 3, lc16 = tid & 7;
    auto load_stage = [&](int kt) {
        float* st = smem + (kt % 3) * STG_F;
        const int k0 = kt * 32;
#pragma unroll
        for (int i = 0; i < 4; i++) {
            const int row = lrow + i * 32;
            cp_async16(st + row * GLDS + lc16 * 4,
                       A + (size_t)(bm + row) * K + k0 + lc16 * 4);
            int rB = bn + row; if (rB >= N) rB = N - 1;   // clamp; junk cols never stored
            cp_async16(st + TILE_F + row * GLDS + lc16 * 4,
                       W + (size_t)rB * K + k0 + lc16 * 4);
        }
        cp_commit();
    };

    // per-lane ldmatrix base offsets (bytes, within a stage)
    // A x4: blocks = (m 0-7 kh0)(m 8-15 kh0)(m 0-7 kh1)(m 8-15 kh1)
    const uint32_t aOff = 4 * ((wm + (lane & 15)) * GLDS + ((lane >> 4) << 2));
    // B x4 pair: blocks = (ntile0 kh0)(ntile0 kh1)(ntile1 kh0)(ntile1 kh1)
    const uint32_t bOff = TILE_BYTES
        + 4 * ((wn + ((lane >> 4) << 3) + (lane & 7)) * GLDS + (((lane >> 3) & 1) << 2));

    load_stage(0);
    load_stage(1);

    for (int kt = 0; kt < KT; kt++) {
        if (kt + 1 < KT) cp_wait<1>(); else cp_wait<0>();
        __syncthreads();                       // stage kt visible; stage (kt+2)%3 free
        if (kt + 2 < KT) load_stage(kt + 2);

        const uint32_t stg = smem_u + (kt % 3) * STG_BYTES;
        const uint32_t aB = stg + aOff;
        const uint32_t bB = stg + bOff;

        uint32_t Af[2][4][4], Bq[2][2][4];
#pragma unroll
        for (int i = 0; i < 4; i++) ldsm_x4(aB + (uint32_t)(i * 16 * GLDS) * 4, Af[0][i]);
#pragma unroll
        for (int p = 0; p < 2; p++) ldsm_x4(bB + (uint32_t)(p * 16 * GLDS) * 4, Bq[0][p]);

#pragma unroll
        for (int kk = 0; kk < 4; kk++) {
            const int cur = kk & 1;
            if (kk < 3) {   // prefetch kk+1 fragments while cur's MMAs drain
                const uint32_t ko = (uint32_t)((kk + 1) * 8) * 4;
#pragma unroll
                for (int i = 0; i < 4; i++)
                    ldsm_x4(aB + ko + (uint32_t)(i * 16 * GLDS) * 4, Af[cur ^ 1][i]);
#pragma unroll
                for (int p = 0; p < 2; p++)
                    ldsm_x4(bB + ko + (uint32_t)(p * 16 * GLDS) * 4, Bq[cur ^ 1][p]);
            }
#pragma unroll
            for (int i = 0; i < 4; i++)
#pragma unroll
                for (int j = 0; j < 4; j++)
                    mma1688(acc[i][j], Af[cur][i], &Bq[cur][j >> 1][(j & 1) * 2]);
        }
    }

    // epilogue: direct float2 stores (+bias)
#pragma unroll
    for (int i = 0; i < 4; i++) {
        const int r0 = bm + wm + i * 16 + gid;
        const int r1 = r0 + 8;
#pragma unroll
        for (int j = 0; j < 4; j++) {
            const int c = wn + j * 8 + tig * 2;
            if (bn + c < N) {
                const float b0 = sBias[c], b1 = sBias[c + 1];
                float2 v0 = {acc[i][j][0] + b0, acc[i][j][1] + b1};
                float2 v1 = {acc[i][j][2] + b0, acc[i][j][3] + b1};
                *(float2*)(C + (size_t)r0 * N + bn + c) = v0;
                *(float2*)(C + (size_t)r1 * N + bn + c) = v1;
            }
        }
    }
}

// ---------------- tf32 rounding prepass (float4 grid-stride) ----------------
__global__ __launch_bounds__(256) void round_tf32_k(
    const float* __restrict__ in, float* __restrict__ out, int n)
{
    int i = (blockIdx.x * 256 + threadIdx.x) * 4;
    if (i < n) {
        float4 v = *(const float4*)(in + i);
        v.x = tf32r(v.x); v.y = tf32r(v.y); v.z = tf32r(v.z); v.w = tf32r(v.w);
        *(float4*)(out + i) = v;
    }
}

// ---------------- RMSNorm (in-place; output tf32-rounded for next GEMM) ------
__global__ __launch_bounds__(256) void rmsnorm_inplace(
    float* __restrict__ data, const float* __restrict__ w, int W)
{
    const int t = blockIdx.x, tid = threadIdx.x;
    float* p = data + (size_t)t * W;
    const int W4 = W >> 2;
    float ss = 0.f;
    for (int i = tid; i < W4; i += 256) {
        float4 v = ((const float4*)p)[i];
        ss += v.x * v.x + v.y * v.y + v.z * v.z + v.w * v.w;
    }
    __shared__ float red[256];
    red[tid] = ss; __syncthreads();
    for (int w2 = 128; w2 > 0; w2 >>= 1) {
        if (tid < w2) red[tid] += red[tid + w2];
        __syncthreads();
    }
    const float inv = rsqrtf(red[0] / (float)W + 1.1920929e-7f);
    for (int i = tid; i < W4; i += 256) {
        float4 v = ((const float4*)p)[i];
        const float4 g = ((const float4*)w)[i];
        v.x = tf32r(v.x * inv * g.x); v.y = tf32r(v.y * inv * g.y);
        v.z = tf32r(v.z * inv * g.z); v.w = tf32r(v.w * inv * g.w);
        ((float4*)p)[i] = v;
    }
}

// ---------------- kv_a post-process: rmsnorm(512, rounded) + rope(last 64) ---
__global__ __launch_bounds__(128) void kv_prep(
    const float* __restrict__ kva, const float* __restrict__ knw,
    const float* __restrict__ cosb, const float* __restrict__ sinb,
    float* __restrict__ kvn, float* __restrict__ kpe, int S)
{
    const int t = blockIdx.x, tid = threadIdx.x;
    const int s = t % S;
    const float* src = kva + (size_t)t * 576;
    float ss = 0.f;
    for (int i = tid; i < 512; i += 128) { float v = src[i]; ss += v * v; }
    __shared__ float red[128];
    red[tid] = ss; __syncthreads();
    for (int w2 = 64; w2 > 0; w2 >>= 1) {
        if (tid < w2) red[tid] += red[tid + w2];
        __syncthreads();
    }
    const float inv = rsqrtf(red[0] / 512.0f + 1.1920929e-7f);
    for (int i = tid; i < 512; i += 128)
        kvn[(size_t)t * 512 + i] = tf32r(src[i] * inv * knw[i]);
    if (tid < 32) {
        const int j = tid;
        const float c = cosb[s * 32 + j], sn = sinb[s * 32 + j];
        const float x0 = src[512 + 2 * j], x1 = src[512 + 2 * j + 1];
        kpe[(size_t)t * 64 + 2 * j]     = x0 * c  - x1 * sn;
        kpe[(size_t)t * 64 + 2 * j + 1] = x0 * sn + x1 * c;
    }
}

// ---------------- per-token attention (output tf32-rounded for wo GEMM) ------
#define ATT_SCALE 0.07216878364870322f  // (128+64)^-0.5
__global__ __launch_bounds__(128) void attn_kernel(
    const float* __restrict__ q, const float* __restrict__ kv,
    const float* __restrict__ kpe, const float* __restrict__ cosb,
    const float* __restrict__ sinb, float* __restrict__ out, int S)
{
    const int t = blockIdx.x, tid = threadIdx.x;
    const int s = t % S;
    __shared__ float qs[3072];
    __shared__ float kvs[16 * 260];
    __shared__ float kp[64];
    __shared__ float sc[16][17];

    const float* qg = q + (size_t)t * 3072;
    for (int i = tid; i < 768; i += 128) ((float4*)qs)[i] = ((const float4*)qg)[i];
    const float* kvg = kv + (size_t)t * 4096;
    for (int i = tid; i < 1024; i += 128) {
        int g = i >> 6, c = i & 63;
        *(float4*)&kvs[g * 260 + c * 4] = *(const float4*)(kvg + g * 256 + c * 4);
    }
    if (tid < 16) ((float4*)kp)[tid] = ((const float4*)(kpe + (size_t)t * 64))[tid];
    __syncthreads();

    for (int p = tid; p < 512; p += 128) {
        const int h = p >> 5, j = p & 31;
        const float c = cosb[s * 32 + j], sn = sinb[s * 32 + j];
        const int i0 = h * 192 + 128 + 2 * j;
        const float x0 = qs[i0], x1 = qs[i0 + 1];
        qs[i0]     = x0 * c  - x1 * sn;
        qs[i0 + 1] = x0 * sn + x1 * c;
    }
    __syncthreads();

    {
        const int h = tid >> 3, g0 = tid & 7, g1 = g0 + 8;
        const float* qh = &qs[h * 192];
        const float* k0 = &kvs[g0 * 260];
        const float* k1 = &kvs[g1 * 260];
        float a0 = 0.f, a1 = 0.f;
#pragma unroll 8
        for (int d = 0; d < 128; d++) { const float qd = qh[d]; a0 += qd * k0[d]; a1 += qd * k1[d]; }
        float pe = 0.f;
        const float* qp = &qs[h * 192 + 128];
#pragma unroll 8
        for (int d = 0; d < 64; d++) pe += qp[d] * kp[d];
        sc[h][g0] = (a0 + pe) * ATT_SCALE;
        sc[h][g1] = (a1 + pe) * ATT_SCALE;
    }
    __syncthreads();

    if (tid < 16) {
        float m = -1e30f;
#pragma unroll
        for (int g = 0; g < 16; g++) m = fmaxf(m, sc[tid][g]);
        float sum = 0.f;
#pragma unroll
        for (int g = 0; g < 16; g++) { const float e = expf(sc[tid][g] - m); sc[tid][g] = e; sum += e; }
        const float r = 1.f / sum;
#pragma unroll
        for (int g = 0; g < 16; g++) sc[tid][g] *= r;
    }
    __syncthreads();

    for (int o = tid; o < 2048; o += 128) {
        const int h = o >> 7, d = o & 127;
        float acc = 0.f;
#pragma unroll
        for (int g = 0; g < 16; g++) acc += sc[h][g] * kvs[g * 260 + 128 + d];
        out[(size_t)t * 2048 + o] = tf32r(acc);
    }
}

// ---------------- host launcher ----------------
static inline void launch_gemm(const float* A, const float* W, const float* bias,
                               float* C, int M, int N, int K)
{
    dim3 grid((N + 127) / 128, M / 128);
    gemm_mma<<<grid, 256, GEMM_SMEM>>>(A, W, bias, C, M, N, K);
}
static inline void launch_round(const float* in, float* out, int n)
{
    round_tf32_k<<<(n / 4 + 255) / 256, 256>>>(in, out, n);
}

extern "C" void kernel_launch(void* const* d_in, const int* in_sizes, int n_in,
                              void* d_out, int out_size)
{
    const float* x     = (const float*)d_in[0];
    const float* fcos  = (const float*)d_in[1];
    const float* fsin  = (const float*)d_in[2];
    const float* wqa   = (const float*)d_in[3];
    const float* wqab  = (const float*)d_in[4];
    const float* qnw   = (const float*)d_in[5];
    const float* wqb   = (const float*)d_in[6];
    const float* wqbb  = (const float*)d_in[7];
    const float* wkva  = (const float*)d_in[8];
    const float* wkvab = (const float*)d_in[9];
    const float* kvnw  = (const float*)d_in[10];
    const float* wkvb  = (const float*)d_in[11];
    const float* wkvbb = (const float*)d_in[12];
    const float* wo    = (const float*)d_in[13];
    const float* wob   = (const float*)d_in[14];
    float* out = (float*)d_out;

    const int T = in_sizes[0] / 2048;   // B*S tokens (8192)
    const int S = in_sizes[1] / 32;     // 2048

    float *qa, *qq, *kva, *kvn, *kpe, *kv, *ao, *xr, *wr;
    cudaGetSymbolAddress((void**)&qa,  g_qa);
    cudaGetSymbolAddress((void**)&qq,  g_q);
    cudaGetSymbolAddress((void**)&kva, g_kva);
    cudaGetSymbolAddress((void**)&kvn, g_kvn);
    cudaGetSymbolAddress((void**)&kpe, g_kpe);
    cudaGetSymbolAddress((void**)&kv,  g_kv);
    cudaGetSymbolAddress((void**)&ao,  g_ao);
    cudaGetSymbolAddress((void**)&xr,  g_xr);
    cudaGetSymbolAddress((void**)&wr,  g_wr);

    cudaFuncSetAttribute(gemm_mma, cudaFuncAttributeMaxDynamicSharedMemorySize, GEMM_SMEM);

    // prepass: round x + all weights to tf32 (bit-exact with per-fragment cvt)
    launch_round(x,    xr,             T * 2048);
    launch_round(wqa,  wr + WQA_OFF,   1536 * 2048);
    launch_round(wqb,  wr + WQB_OFF,   3072 * 1536);
    launch_round(wkva, wr + WKVA_OFF,  576 * 2048);
    launch_round(wkvb, wr + WKVB_OFF,  4096 * 512);
    launch_round(wo,   wr + WO_OFF,    2048 * 2048);

    // q path
    launch_gemm(xr,  wr + WQA_OFF,  wqab,  qa,  T, 1536, 2048);
    rmsnorm_inplace<<<T, 256>>>(qa, qnw, 1536);
    launch_gemm(qa,  wr + WQB_OFF,  wqbb,  qq,  T, 3072, 1536);
    // kv path
    launch_gemm(xr,  wr + WKVA_OFF, wkvab, kva, T, 576,  2048);
    kv_prep<<<T, 128>>>(kva, kvnw, fcos, fsin, kvn, kpe, S);
    launch_gemm(kvn, wr + WKVB_OFF, wkvbb, kv,  T, 4096, 512);
    // attention + output projection
    attn_kernel<<<T, 128>>>(qq, kv, kpe, fcos, fsin, ao, S);
    launch_gemm(ao,  wr + WO_OFF,   wob,   out, T, 2048, 2048);
}